// round 16
// baseline (speedup 1.0000x reference)
#include <cuda_runtime.h>
#include <cuda_fp16.h>
#include <cuda_bf16.h>
#include <cstdint>

#define N_NODES 100000
#define N_EDGES 1600000
#define IN_F    128
#define HEADS   8
#define OUT_F   16
#define HD      128   // HEADS*OUT_F
#define NEG_SLOPE 0.2f

// ---------------- scratch (device globals; no allocation allowed) ------------
__device__ __align__(16) float  g_h  [N_NODES * HD];   // fp32 projected features
__device__ __align__(16) float  g_el [N_NODES * HEADS];
__device__ __align__(16) float  g_er [N_NODES * HEADS];
__device__ __align__(16) int    g_deg   [N_NODES];     // zero-init; re-zeroed by k_agg
__device__ __align__(16) int    g_off   [N_NODES + 4];
__device__ __align__(16) int    g_cursor[N_NODES];
__device__ __align__(16) int    g_csr_src[N_EDGES];
__device__ int g_bsum[32];

// -------- L2 cache-policy wrappers (createpolicy + cache_hint) ----------------
__device__ __forceinline__ uint64_t mk_policy_evict_last() {
    uint64_t p;
    asm("createpolicy.fractional.L2::evict_last.b64 %0, 1.0;" : "=l"(p));
    return p;
}
__device__ __forceinline__ uint64_t mk_policy_evict_first() {
    uint64_t p;
    asm("createpolicy.fractional.L2::evict_first.b64 %0, 1.0;" : "=l"(p));
    return p;
}
__device__ __forceinline__ float4 ldg_v4_hint(const float4* p, uint64_t pol) {
    float4 v;
    asm("ld.global.nc.L2::cache_hint.v4.f32 {%0,%1,%2,%3}, [%4], %5;"
        : "=f"(v.x), "=f"(v.y), "=f"(v.z), "=f"(v.w) : "l"(p), "l"(pol));
    return v;
}
__device__ __forceinline__ float ldg_f_hint(const float* p, uint64_t pol) {
    float v;
    asm("ld.global.nc.L2::cache_hint.f32 %0, [%1], %2;" : "=f"(v) : "l"(p), "l"(pol));
    return v;
}
__device__ __forceinline__ int ldg_i_hint(const int* p, uint64_t pol) {
    int v;
    asm("ld.global.nc.L2::cache_hint.b32 %0, [%1], %2;" : "=r"(v) : "l"(p), "l"(pol));
    return v;
}
__device__ __forceinline__ void stg_v4_hint(float4* p, float4 v, uint64_t pol) {
    asm volatile("st.global.L2::cache_hint.v4.f32 [%0], {%1,%2,%3,%4}, %5;"
                 :: "l"(p), "f"(v.x), "f"(v.y), "f"(v.z), "f"(v.w), "l"(pol) : "memory");
}

// -------- tensor-core helpers (sm_80-class mma.sync / ldmatrix) ----------------
__device__ __forceinline__ uint32_t smem_u32(const void* p) {
    uint32_t a;
    asm("{ .reg .u64 t; cvta.to.shared.u64 t, %1; cvt.u32.u64 %0, t; }" : "=r"(a) : "l"(p));
    return a;
}
__device__ __forceinline__ void ldsm_x4(uint32_t r[4], uint32_t addr) {
    asm volatile("ldmatrix.sync.aligned.m8n8.x4.shared.b16 {%0,%1,%2,%3}, [%4];"
                 : "=r"(r[0]), "=r"(r[1]), "=r"(r[2]), "=r"(r[3]) : "r"(addr));
}
__device__ __forceinline__ void mma_bf16(float d[4], const uint32_t a[4], const uint32_t b[2]) {
    asm volatile("mma.sync.aligned.m16n8k16.row.col.f32.bf16.bf16.f32 "
                 "{%0,%1,%2,%3}, {%4,%5,%6,%7}, {%8,%9}, {%0,%1,%2,%3};"
                 : "+f"(d[0]), "+f"(d[1]), "+f"(d[2]), "+f"(d[3])
                 : "r"(a[0]), "r"(a[1]), "r"(a[2]), "r"(a[3]), "r"(b[0]), "r"(b[1]));
}
__device__ __forceinline__ uint32_t bf2(float a, float b) {
    __nv_bfloat162 t = __floats2bfloat162_rn(a, b);
    return *reinterpret_cast<uint32_t*>(&t);
}

// ---------------- K1: tensor-core split-bf16 projection (R15 exact) ------------
#define PROJ_BLOCK 256
#define N_TILES (N_NODES / 16)              // 6250 exactly
#define WSTRIDE 136
#define OFF_WHI 0
#define OFF_WLO (OFF_WHI + 128 * 272)
#define OFF_AHI (OFF_WLO + 128 * 272)
#define OFF_ALO (OFF_AHI + 16 * 272)
#define OFF_CST (OFF_ALO + 16 * 272)
#define OFF_AL  (OFF_CST + 16 * 128 * 4)
#define OFF_AR  (OFF_AL + 512)
#define PROJ_SMEM (OFF_AR + 512)            // 87552

__global__ void __launch_bounds__(PROJ_BLOCK, 2)
k_proj(const float* __restrict__ feats, const float* __restrict__ W,
       const float* __restrict__ attn_l, const float* __restrict__ attn_r)
{
    extern __shared__ char smem[];
    __nv_bfloat16* Whi = (__nv_bfloat16*)(smem + OFF_WHI);
    __nv_bfloat16* Wlo = (__nv_bfloat16*)(smem + OFF_WLO);
    float* Cst = (float*)(smem + OFF_CST);
    float* al  = (float*)(smem + OFF_AL);
    float* ar  = (float*)(smem + OFF_AR);
    const uint32_t sb = smem_u32(smem);

    const int tid = threadIdx.x;
    const uint64_t pol_last  = mk_policy_evict_last();
    const uint64_t pol_first = mk_policy_evict_first();

    for (int i = tid; i < 128 * 128 / 4; i += PROJ_BLOCK) {
        int k = i >> 5, n0 = (i & 31) * 4;
        float4 w = ((const float4*)W)[i];
        float wv[4] = {w.x, w.y, w.z, w.w};
        #pragma unroll
        for (int j = 0; j < 4; j++) {
            float v = wv[j];
            __nv_bfloat16 hi = __float2bfloat16(v);
            __nv_bfloat16 lo = __float2bfloat16(v - __bfloat162float(hi));
            Whi[(n0 + j) * WSTRIDE + k] = hi;
            Wlo[(n0 + j) * WSTRIDE + k] = lo;
        }
    }
    if (tid < 128) { al[tid] = attn_l[tid]; ar[tid] = attn_r[tid]; }
    __syncthreads();

    const int warp = tid >> 5, lane = tid & 31;
    const int n0 = warp * 16;

    uint32_t bhi[8][2][2], blo[8][2][2];
    {
        const uint32_t* Whw = (const uint32_t*)Whi;
        const uint32_t* Wlw = (const uint32_t*)Wlo;
        #pragma unroll
        for (int k = 0; k < 8; k++)
            #pragma unroll
            for (int nt = 0; nt < 2; nt++) {
                int n = n0 + nt * 8 + (lane >> 2);
                int base = n * 68 + k * 8 + (lane & 3);
                bhi[k][nt][0] = Whw[base];     bhi[k][nt][1] = Whw[base + 4];
                blo[k][nt][0] = Wlw[base];     blo[k][nt][1] = Wlw[base + 4];
            }
    }

    const int erow = tid >> 4, eseg = tid & 15;
    const int ehead = eseg >> 1;

    for (int tile = blockIdx.x; tile < N_TILES; tile += gridDim.x) {
        const int row0 = tile * 16;

        #pragma unroll
        for (int j = 0; j < 2; j++) {
            int idx = tid + j * 256;
            int r = idx >> 5, c4 = idx & 31;
            float4 f = ldg_v4_hint(((const float4*)(feats + (row0 + r) * IN_F)) + c4, pol_first);
            __nv_bfloat16 h0 = __float2bfloat16(f.x);
            __nv_bfloat16 h1 = __float2bfloat16(f.y);
            __nv_bfloat16 h2 = __float2bfloat16(f.z);
            __nv_bfloat16 h3 = __float2bfloat16(f.w);
            uint2 hu = make_uint2(bf2(__bfloat162float(h0), __bfloat162float(h1)),
                                  bf2(__bfloat162float(h2), __bfloat162float(h3)));
            uint2 lu = make_uint2(bf2(f.x - __bfloat162float(h0), f.y - __bfloat162float(h1)),
                                  bf2(f.z - __bfloat162float(h2), f.w - __bfloat162float(h3)));
            *(uint2*)(smem + OFF_AHI + r * 272 + c4 * 8) = hu;
            *(uint2*)(smem + OFF_ALO + r * 272 + c4 * 8) = lu;
        }
        __syncthreads();

        float acc[2][4] = {{0.f, 0.f, 0.f, 0.f}, {0.f, 0.f, 0.f, 0.f}};
        const uint32_t arow = (uint32_t)((lane & 7) + ((lane >> 3) & 1) * 8);
        const uint32_t acol = (uint32_t)((lane >> 4) * 16);
        #pragma unroll
        for (int k = 0; k < 8; k++) {
            uint32_t a_hi[4], a_lo[4];
            uint32_t aoff = arow * 272 + (uint32_t)(k * 32) + acol;
            ldsm_x4(a_hi, sb + OFF_AHI + aoff);
            ldsm_x4(a_lo, sb + OFF_ALO + aoff);
            #pragma unroll
            for (int nt = 0; nt < 2; nt++) {
                mma_bf16(acc[nt], a_hi, bhi[k][nt]);
                mma_bf16(acc[nt], a_hi, blo[k][nt]);
                mma_bf16(acc[nt], a_lo, bhi[k][nt]);
            }
        }

        {
            int rowA = lane >> 2;
            int colb = 2 * (lane & 3);
            #pragma unroll
            for (int nt = 0; nt < 2; nt++) {
                int c = n0 + nt * 8 + colb;
                *(float2*)(Cst + rowA * 128 + c)       = make_float2(acc[nt][0], acc[nt][1]);
                *(float2*)(Cst + (rowA + 8) * 128 + c) = make_float2(acc[nt][2], acc[nt][3]);
            }
        }
        __syncthreads();

        {
            int grow = row0 + erow;
            const float* cr = Cst + erow * 128 + eseg * 8;
            float4 c0 = ((const float4*)cr)[0];
            float4 c1 = ((const float4*)cr)[1];
            stg_v4_hint(((float4*)(g_h + grow * HD + eseg * 8)), c0, pol_last);
            stg_v4_hint(((float4*)(g_h + grow * HD + eseg * 8)) + 1, c1, pol_last);
            const float* alp = al + eseg * 8;
            const float* arp = ar + eseg * 8;
            float pl = c0.x*alp[0] + c0.y*alp[1] + c0.z*alp[2] + c0.w*alp[3]
                     + c1.x*alp[4] + c1.y*alp[5] + c1.z*alp[6] + c1.w*alp[7];
            float pr = c0.x*arp[0] + c0.y*arp[1] + c0.z*arp[2] + c0.w*arp[3]
                     + c1.x*arp[4] + c1.y*arp[5] + c1.z*arp[6] + c1.w*arp[7];
            pl += __shfl_xor_sync(0xffffffffu, pl, 1);
            pr += __shfl_xor_sync(0xffffffffu, pr, 1);
            if ((eseg & 1) == 0) {
                g_el[grow * HEADS + ehead] = pl;
                g_er[grow * HEADS + ehead] = pr;
            }
        }
        __syncthreads();
    }
}

// ---------------- CSR build: hist(8/thr) -> scan1 -> scan3' -> scatter(8/thr) --
__global__ void __launch_bounds__(256)
k_hist(const int* __restrict__ dst)
{
    int i = blockIdx.x * 256 + threadIdx.x;          // 8 edges per thread
    if (i * 8 >= N_EDGES) return;
    int4 a = ((const int4*)dst)[i * 2];
    int4 b = ((const int4*)dst)[i * 2 + 1];
    atomicAdd(&g_deg[a.x], 1); atomicAdd(&g_deg[a.y], 1);
    atomicAdd(&g_deg[a.z], 1); atomicAdd(&g_deg[a.w], 1);
    atomicAdd(&g_deg[b.x], 1); atomicAdd(&g_deg[b.y], 1);
    atomicAdd(&g_deg[b.z], 1); atomicAdd(&g_deg[b.w], 1);
}

#define SCAN_BLOCKS ((N_NODES + 4095) / 4096)   // 25

__global__ void __launch_bounds__(1024)
k_scan1()
{
    __shared__ int wsum[32];
    const int tid = threadIdx.x, lane = tid & 31, warp = tid >> 5;
    const int i0 = blockIdx.x * 4096 + tid * 4;

    int4 v = (i0 < N_NODES) ? ((const int4*)g_deg)[i0 >> 2] : make_int4(0, 0, 0, 0);
    int t = v.x + v.y + v.z + v.w;
    int x = t;
    #pragma unroll
    for (int o = 1; o < 32; o <<= 1) {
        int y = __shfl_up_sync(0xffffffffu, x, o);
        if (lane >= o) x += y;
    }
    if (lane == 31) wsum[warp] = x;
    __syncthreads();
    if (warp == 0) {
        int s = wsum[lane];
        #pragma unroll
        for (int o = 1; o < 32; o <<= 1) {
            int y = __shfl_up_sync(0xffffffffu, s, o);
            if (lane >= o) s += y;
        }
        wsum[lane] = s;
    }
    __syncthreads();
    int warpoff = (warp == 0) ? 0 : wsum[warp - 1];
    int excl = warpoff + x - t;
    if (i0 < N_NODES) {
        int4 o;
        o.x = excl;
        o.y = o.x + v.x;
        o.z = o.y + v.y;
        o.w = o.z + v.z;
        ((int4*)g_off)[i0 >> 2] = o;
    }
    if (tid == 0) g_bsum[blockIdx.x] = wsum[31];
}

// scan3': each block recomputes the 25-element block-sum prefix itself (warp 0),
// then applies it — k_scan2 launch eliminated.
__global__ void __launch_bounds__(1024)
k_scan3()
{
    __shared__ int s_boff;
    const int tid = threadIdx.x;
    if (tid < 32) {
        int v = (tid < SCAN_BLOCKS) ? g_bsum[tid] : 0;
        int x = v;
        #pragma unroll
        for (int o = 1; o < 32; o <<= 1) {
            int y = __shfl_up_sync(0xffffffffu, x, o);
            if (tid >= o) x += y;
        }
        // exclusive prefix for this block
        if (tid == (int)blockIdx.x) s_boff = x - v;
    }
    __syncthreads();
    const int boff = s_boff;
    const int i0 = blockIdx.x * 4096 + tid * 4;
    if (i0 < N_NODES) {
        int4 o = ((const int4*)g_off)[i0 >> 2];
        o.x += boff; o.y += boff; o.z += boff; o.w += boff;
        ((int4*)g_off)[i0 >> 2] = o;
        ((int4*)g_cursor)[i0 >> 2] = o;
    }
    if (blockIdx.x == 0 && tid == 0) g_off[N_NODES] = N_EDGES;
}

__global__ void __launch_bounds__(256)
k_scatter(const int* __restrict__ src, const int* __restrict__ dst)
{
    int i = blockIdx.x * 256 + threadIdx.x;          // 8 edges per thread
    if (i * 8 >= N_EDGES) return;
    int4 sa = ((const int4*)src)[i * 2];
    int4 sb = ((const int4*)src)[i * 2 + 1];
    int4 da = ((const int4*)dst)[i * 2];
    int4 db = ((const int4*)dst)[i * 2 + 1];
    int p0 = atomicAdd(&g_cursor[da.x], 1);
    int p1 = atomicAdd(&g_cursor[da.y], 1);
    int p2 = atomicAdd(&g_cursor[da.z], 1);
    int p3 = atomicAdd(&g_cursor[da.w], 1);
    int p4 = atomicAdd(&g_cursor[db.x], 1);
    int p5 = atomicAdd(&g_cursor[db.y], 1);
    int p6 = atomicAdd(&g_cursor[db.z], 1);
    int p7 = atomicAdd(&g_cursor[db.w], 1);
    g_csr_src[p0] = sa.x; g_csr_src[p1] = sa.y;
    g_csr_src[p2] = sa.z; g_csr_src[p3] = sa.w;
    g_csr_src[p4] = sb.x; g_csr_src[p5] = sb.y;
    g_csr_src[p6] = sb.z; g_csr_src[p7] = sb.w;
}

// ---------------- K3: warp per dst node, batched-exp (R15 + deg re-zero) -------
__global__ void __launch_bounds__(256)
k_agg(const float* __restrict__ bias, float* __restrict__ out)
{
    const int d = (blockIdx.x * 256 + threadIdx.x) >> 5;
    const int lane = threadIdx.x & 31;
    if (d >= N_NODES) return;
    const int q = lane >> 3;
    const int h = lane & 7;
    const int ghead = lane >> 2;

    const uint64_t pol_last  = mk_policy_evict_last();
    const uint64_t pol_first = mk_policy_evict_first();

    const int start = g_off[d], end = g_off[d + 1];
    const float erh = g_er[d * HEADS + h];
    if (lane == 0) g_deg[d] = 0;     // reset histogram for the next graph replay

    float sum = 0.f;
    float4 acc = {0.f, 0.f, 0.f, 0.f};

    for (int base = start; base < end; base += 32) {
        const int idx = base + lane;
        const int myS = (idx < end) ? ldg_i_hint(g_csr_src + idx, pol_first) : 0;
        const int cnt = min(32, end - base);

        for (int t = 0; t < cnt; t += 4) {
            int se = __shfl_sync(0xffffffffu, myS, t + q);
            float a = ldg_f_hint(g_el + se * HEADS + h, pol_last) + erh;
            a = fmaxf(a, 0.f) + NEG_SLOPE * fminf(a, 0.f);
            float ex = (t + q < cnt) ? __expf(a) : 0.f;
            sum += ex;

            #pragma unroll
            for (int u = 0; u < 4; u++) {
                int s = __shfl_sync(0xffffffffu, myS, t + u);
                float exh = __shfl_sync(0xffffffffu, ex, u * 8 + ghead);
                float4 hv = ldg_v4_hint(((const float4*)(g_h + s * HD)) + lane, pol_last);
                acc.x += exh * hv.x; acc.y += exh * hv.y;
                acc.z += exh * hv.z; acc.w += exh * hv.w;
            }
        }
    }

    sum += __shfl_xor_sync(0xffffffffu, sum, 8);
    sum += __shfl_xor_sync(0xffffffffu, sum, 16);
    float sumh = __shfl_sync(0xffffffffu, sum, ghead);

    float inv = (end > start) ? 1.f / sumh : 0.f;
    float4 hd = ldg_v4_hint(((const float4*)(g_h + d * HD)) + lane, pol_last);
    float4 b  = ((const float4*)bias)[lane];
    float4 o;
    o.x = acc.x * inv + hd.x + b.x;
    o.y = acc.y * inv + hd.y + b.y;
    o.z = acc.z * inv + hd.z + b.z;
    o.w = acc.w * inv + hd.w + b.w;
    stg_v4_hint(((float4*)(out + d * HD)) + lane, o, pol_first);
}

// ---------------- launch ---------------------------------------------------------
extern "C" void kernel_launch(void* const* d_in, const int* in_sizes, int n_in,
                              void* d_out, int out_size)
{
    const float* feats  = (const float*)d_in[0];
    const float* W      = (const float*)d_in[1];
    const float* attn_l = (const float*)d_in[2];
    const float* attn_r = (const float*)d_in[3];
    const float* bias   = (const float*)d_in[4];
    const int*   src    = (const int*)d_in[5];
    const int*   dst    = (const int*)d_in[6];
    float* out = (float*)d_out;

    cudaFuncSetAttribute(k_proj, cudaFuncAttributeMaxDynamicSharedMemorySize, PROJ_SMEM);

    cudaStream_t side;
    cudaEvent_t ev_fork, ev_join;
    cudaStreamCreateWithFlags(&side, cudaStreamNonBlocking);
    cudaEventCreateWithFlags(&ev_fork, cudaEventDisableTiming);
    cudaEventCreateWithFlags(&ev_join, cudaEventDisableTiming);

    cudaEventRecord(ev_fork, 0);
    cudaStreamWaitEvent(side, ev_fork, 0);

    // CSR build chain on side stream (g_deg arrives zeroed: static init on the
    // first call, then re-zeroed by k_agg at the end of every launch/replay)
    k_hist<<<(N_EDGES / 8 + 255) / 256, 256, 0, side>>>(dst);
    k_scan1<<<SCAN_BLOCKS, 1024, 0, side>>>();
    k_scan3<<<SCAN_BLOCKS, 1024, 0, side>>>();
    k_scatter<<<(N_EDGES / 8 + 255) / 256, 256, 0, side>>>(src, dst);
    cudaEventRecord(ev_join, side);

    // tensor-core projection on the main stream, concurrent with CSR build
    k_proj<<<296, PROJ_BLOCK, PROJ_SMEM>>>(feats, W, attn_l, attn_r);

    cudaStreamWaitEvent(0, ev_join, 0);
    k_agg<<<(N_NODES * 32 + 255) / 256, 256>>>(bias, out);
}

// round 17
// speedup vs baseline: 1.0433x; 1.0433x over previous
#include <cuda_runtime.h>
#include <cuda_fp16.h>
#include <cuda_bf16.h>
#include <cstdint>

#define N_NODES 100000
#define N_EDGES 1600000
#define IN_F    128
#define HEADS   8
#define OUT_F   16
#define HD      128   // HEADS*OUT_F
#define NEG_SLOPE 0.2f

// ---------------- scratch (device globals; no allocation allowed) ------------
__device__ __align__(16) float  g_h  [N_NODES * HD];   // fp32 projected features
__device__ __align__(16) float  g_el [N_NODES * HEADS];
__device__ __align__(16) float  g_er [N_NODES * HEADS];
__device__ __align__(16) int    g_deg   [N_NODES];     // zero-init; re-zeroed by k_agg
__device__ __align__(16) int    g_off   [N_NODES + 4];
__device__ __align__(16) int    g_cursor[N_NODES];
__device__ __align__(16) int    g_csr_src[N_EDGES];
__device__ int g_chain[32];                             // scan chain; re-zeroed by k_agg

// -------- L2 cache-policy wrappers (createpolicy + cache_hint) ----------------
__device__ __forceinline__ uint64_t mk_policy_evict_last() {
    uint64_t p;
    asm("createpolicy.fractional.L2::evict_last.b64 %0, 1.0;" : "=l"(p));
    return p;
}
__device__ __forceinline__ uint64_t mk_policy_evict_first() {
    uint64_t p;
    asm("createpolicy.fractional.L2::evict_first.b64 %0, 1.0;" : "=l"(p));
    return p;
}
__device__ __forceinline__ float4 ldg_v4_hint(const float4* p, uint64_t pol) {
    float4 v;
    asm("ld.global.nc.L2::cache_hint.v4.f32 {%0,%1,%2,%3}, [%4], %5;"
        : "=f"(v.x), "=f"(v.y), "=f"(v.z), "=f"(v.w) : "l"(p), "l"(pol));
    return v;
}
__device__ __forceinline__ float ldg_f_hint(const float* p, uint64_t pol) {
    float v;
    asm("ld.global.nc.L2::cache_hint.f32 %0, [%1], %2;" : "=f"(v) : "l"(p), "l"(pol));
    return v;
}
__device__ __forceinline__ int ldg_i_hint(const int* p, uint64_t pol) {
    int v;
    asm("ld.global.nc.L2::cache_hint.b32 %0, [%1], %2;" : "=r"(v) : "l"(p), "l"(pol));
    return v;
}
__device__ __forceinline__ void stg_v4_hint(float4* p, float4 v, uint64_t pol) {
    asm volatile("st.global.L2::cache_hint.v4.f32 [%0], {%1,%2,%3,%4}, %5;"
                 :: "l"(p), "f"(v.x), "f"(v.y), "f"(v.z), "f"(v.w), "l"(pol) : "memory");
}

// -------- tensor-core helpers (sm_80-class mma.sync / ldmatrix) ----------------
__device__ __forceinline__ uint32_t smem_u32(const void* p) {
    uint32_t a;
    asm("{ .reg .u64 t; cvta.to.shared.u64 t, %1; cvt.u32.u64 %0, t; }" : "=r"(a) : "l"(p));
    return a;
}
__device__ __forceinline__ void ldsm_x4(uint32_t r[4], uint32_t addr) {
    asm volatile("ldmatrix.sync.aligned.m8n8.x4.shared.b16 {%0,%1,%2,%3}, [%4];"
                 : "=r"(r[0]), "=r"(r[1]), "=r"(r[2]), "=r"(r[3]) : "r"(addr));
}
__device__ __forceinline__ void mma_bf16(float d[4], const uint32_t a[4], const uint32_t b[2]) {
    asm volatile("mma.sync.aligned.m16n8k16.row.col.f32.bf16.bf16.f32 "
                 "{%0,%1,%2,%3}, {%4,%5,%6,%7}, {%8,%9}, {%0,%1,%2,%3};"
                 : "+f"(d[0]), "+f"(d[1]), "+f"(d[2]), "+f"(d[3])
                 : "r"(a[0]), "r"(a[1]), "r"(a[2]), "r"(a[3]), "r"(b[0]), "r"(b[1]));
}
__device__ __forceinline__ uint32_t bf2(float a, float b) {
    __nv_bfloat162 t = __floats2bfloat162_rn(a, b);
    return *reinterpret_cast<uint32_t*>(&t);
}

// ---------------- K1: tensor-core split-bf16 projection (R15 exact) ------------
#define PROJ_BLOCK 256
#define N_TILES (N_NODES / 16)              // 6250 exactly
#define WSTRIDE 136
#define OFF_WHI 0
#define OFF_WLO (OFF_WHI + 128 * 272)
#define OFF_AHI (OFF_WLO + 128 * 272)
#define OFF_ALO (OFF_AHI + 16 * 272)
#define OFF_CST (OFF_ALO + 16 * 272)
#define OFF_AL  (OFF_CST + 16 * 128 * 4)
#define OFF_AR  (OFF_AL + 512)
#define PROJ_SMEM (OFF_AR + 512)            // 87552

__global__ void __launch_bounds__(PROJ_BLOCK, 2)
k_proj(const float* __restrict__ feats, const float* __restrict__ W,
       const float* __restrict__ attn_l, const float* __restrict__ attn_r)
{
    extern __shared__ char smem[];
    __nv_bfloat16* Whi = (__nv_bfloat16*)(smem + OFF_WHI);
    __nv_bfloat16* Wlo = (__nv_bfloat16*)(smem + OFF_WLO);
    float* Cst = (float*)(smem + OFF_CST);
    float* al  = (float*)(smem + OFF_AL);
    float* ar  = (float*)(smem + OFF_AR);
    const uint32_t sb = smem_u32(smem);

    const int tid = threadIdx.x;
    const uint64_t pol_last  = mk_policy_evict_last();
    const uint64_t pol_first = mk_policy_evict_first();

    for (int i = tid; i < 128 * 128 / 4; i += PROJ_BLOCK) {
        int k = i >> 5, n0 = (i & 31) * 4;
        float4 w = ((const float4*)W)[i];
        float wv[4] = {w.x, w.y, w.z, w.w};
        #pragma unroll
        for (int j = 0; j < 4; j++) {
            float v = wv[j];
            __nv_bfloat16 hi = __float2bfloat16(v);
            __nv_bfloat16 lo = __float2bfloat16(v - __bfloat162float(hi));
            Whi[(n0 + j) * WSTRIDE + k] = hi;
            Wlo[(n0 + j) * WSTRIDE + k] = lo;
        }
    }
    if (tid < 128) { al[tid] = attn_l[tid]; ar[tid] = attn_r[tid]; }
    __syncthreads();

    const int warp = tid >> 5, lane = tid & 31;
    const int n0 = warp * 16;

    uint32_t bhi[8][2][2], blo[8][2][2];
    {
        const uint32_t* Whw = (const uint32_t*)Whi;
        const uint32_t* Wlw = (const uint32_t*)Wlo;
        #pragma unroll
        for (int k = 0; k < 8; k++)
            #pragma unroll
            for (int nt = 0; nt < 2; nt++) {
                int n = n0 + nt * 8 + (lane >> 2);
                int base = n * 68 + k * 8 + (lane & 3);
                bhi[k][nt][0] = Whw[base];     bhi[k][nt][1] = Whw[base + 4];
                blo[k][nt][0] = Wlw[base];     blo[k][nt][1] = Wlw[base + 4];
            }
    }

    const int erow = tid >> 4, eseg = tid & 15;
    const int ehead = eseg >> 1;

    for (int tile = blockIdx.x; tile < N_TILES; tile += gridDim.x) {
        const int row0 = tile * 16;

        #pragma unroll
        for (int j = 0; j < 2; j++) {
            int idx = tid + j * 256;
            int r = idx >> 5, c4 = idx & 31;
            float4 f = ldg_v4_hint(((const float4*)(feats + (row0 + r) * IN_F)) + c4, pol_first);
            __nv_bfloat16 h0 = __float2bfloat16(f.x);
            __nv_bfloat16 h1 = __float2bfloat16(f.y);
            __nv_bfloat16 h2 = __float2bfloat16(f.z);
            __nv_bfloat16 h3 = __float2bfloat16(f.w);
            uint2 hu = make_uint2(bf2(__bfloat162float(h0), __bfloat162float(h1)),
                                  bf2(__bfloat162float(h2), __bfloat162float(h3)));
            uint2 lu = make_uint2(bf2(f.x - __bfloat162float(h0), f.y - __bfloat162float(h1)),
                                  bf2(f.z - __bfloat162float(h2), f.w - __bfloat162float(h3)));
            *(uint2*)(smem + OFF_AHI + r * 272 + c4 * 8) = hu;
            *(uint2*)(smem + OFF_ALO + r * 272 + c4 * 8) = lu;
        }
        __syncthreads();

        float acc[2][4] = {{0.f, 0.f, 0.f, 0.f}, {0.f, 0.f, 0.f, 0.f}};
        const uint32_t arow = (uint32_t)((lane & 7) + ((lane >> 3) & 1) * 8);
        const uint32_t acol = (uint32_t)((lane >> 4) * 16);
        #pragma unroll
        for (int k = 0; k < 8; k++) {
            uint32_t a_hi[4], a_lo[4];
            uint32_t aoff = arow * 272 + (uint32_t)(k * 32) + acol;
            ldsm_x4(a_hi, sb + OFF_AHI + aoff);
            ldsm_x4(a_lo, sb + OFF_ALO + aoff);
            #pragma unroll
            for (int nt = 0; nt < 2; nt++) {
                mma_bf16(acc[nt], a_hi, bhi[k][nt]);
                mma_bf16(acc[nt], a_hi, blo[k][nt]);
                mma_bf16(acc[nt], a_lo, bhi[k][nt]);
            }
        }

        {
            int rowA = lane >> 2;
            int colb = 2 * (lane & 3);
            #pragma unroll
            for (int nt = 0; nt < 2; nt++) {
                int c = n0 + nt * 8 + colb;
                *(float2*)(Cst + rowA * 128 + c)       = make_float2(acc[nt][0], acc[nt][1]);
                *(float2*)(Cst + (rowA + 8) * 128 + c) = make_float2(acc[nt][2], acc[nt][3]);
            }
        }
        __syncthreads();

        {
            int grow = row0 + erow;
            const float* cr = Cst + erow * 128 + eseg * 8;
            float4 c0 = ((const float4*)cr)[0];
            float4 c1 = ((const float4*)cr)[1];
            stg_v4_hint(((float4*)(g_h + grow * HD + eseg * 8)), c0, pol_last);
            stg_v4_hint(((float4*)(g_h + grow * HD + eseg * 8)) + 1, c1, pol_last);
            const float* alp = al + eseg * 8;
            const float* arp = ar + eseg * 8;
            float pl = c0.x*alp[0] + c0.y*alp[1] + c0.z*alp[2] + c0.w*alp[3]
                     + c1.x*alp[4] + c1.y*alp[5] + c1.z*alp[6] + c1.w*alp[7];
            float pr = c0.x*arp[0] + c0.y*arp[1] + c0.z*arp[2] + c0.w*arp[3]
                     + c1.x*arp[4] + c1.y*arp[5] + c1.z*arp[6] + c1.w*arp[7];
            pl += __shfl_xor_sync(0xffffffffu, pl, 1);
            pr += __shfl_xor_sync(0xffffffffu, pr, 1);
            if ((eseg & 1) == 0) {
                g_el[grow * HEADS + ehead] = pl;
                g_er[grow * HEADS + ehead] = pr;
            }
        }
        __syncthreads();
    }
}

// ---------------- CSR build: hist(4/thr) -> merged scan -> scatter(4/thr) ------
__global__ void __launch_bounds__(256)
k_hist(const int* __restrict__ dst)
{
    int i = blockIdx.x * 256 + threadIdx.x;          // 4 edges per thread
    if (i * 4 >= N_EDGES) return;
    int4 d4 = ((const int4*)dst)[i];
    atomicAdd(&g_deg[d4.x], 1);
    atomicAdd(&g_deg[d4.y], 1);
    atomicAdd(&g_deg[d4.z], 1);
    atomicAdd(&g_deg[d4.w], 1);
}

#define SCAN_BLOCKS ((N_NODES + 4095) / 4096)   // 25

// single-pass scan: local block scan + chained prefix publication via g_chain.
// g_chain[b] == 0 means "not ready"; else value = inclusive_prefix(b) + 1.
// g_chain is zeroed by the previous launch's k_agg (and statically at init).
__global__ void __launch_bounds__(1024)
k_scan()
{
    __shared__ int wsum[32];
    __shared__ int s_boff;
    const int tid = threadIdx.x, lane = tid & 31, warp = tid >> 5;
    const int i0 = blockIdx.x * 4096 + tid * 4;

    int4 v = (i0 < N_NODES) ? ((const int4*)g_deg)[i0 >> 2] : make_int4(0, 0, 0, 0);
    int t = v.x + v.y + v.z + v.w;
    int x = t;
    #pragma unroll
    for (int o = 1; o < 32; o <<= 1) {
        int y = __shfl_up_sync(0xffffffffu, x, o);
        if (lane >= o) x += y;
    }
    if (lane == 31) wsum[warp] = x;
    __syncthreads();
    if (warp == 0) {
        int s = wsum[lane];
        #pragma unroll
        for (int o = 1; o < 32; o <<= 1) {
            int y = __shfl_up_sync(0xffffffffu, s, o);
            if (lane >= o) s += y;
        }
        wsum[lane] = s;
    }
    __syncthreads();
    const int blocktotal = wsum[31];

    // chained exclusive block prefix (25 blocks, all resident)
    if (tid == 0) {
        int prefix = 0;
        if (blockIdx.x > 0) {
            int vchain;
            do { vchain = atomicAdd(&g_chain[blockIdx.x - 1], 0); } while (vchain == 0);
            prefix = vchain - 1;
        }
        atomicExch(&g_chain[blockIdx.x], prefix + blocktotal + 1);
        s_boff = prefix;
    }
    __syncthreads();
    const int boff = s_boff;

    int warpoff = (warp == 0) ? 0 : wsum[warp - 1];
    int excl = boff + warpoff + x - t;
    if (i0 < N_NODES) {
        int4 o;
        o.x = excl;
        o.y = o.x + v.x;
        o.z = o.y + v.y;
        o.w = o.z + v.z;
        ((int4*)g_off)[i0 >> 2] = o;
        ((int4*)g_cursor)[i0 >> 2] = o;
    }
    if (blockIdx.x == 0 && tid == 0) g_off[N_NODES] = N_EDGES;
}

__global__ void __launch_bounds__(256)
k_scatter(const int* __restrict__ src, const int* __restrict__ dst)
{
    int i = blockIdx.x * 256 + threadIdx.x;          // 4 edges per thread
    if (i * 4 >= N_EDGES) return;
    int4 s4 = ((const int4*)src)[i];
    int4 d4 = ((const int4*)dst)[i];
    int p0 = atomicAdd(&g_cursor[d4.x], 1);
    int p1 = atomicAdd(&g_cursor[d4.y], 1);
    int p2 = atomicAdd(&g_cursor[d4.z], 1);
    int p3 = atomicAdd(&g_cursor[d4.w], 1);
    g_csr_src[p0] = s4.x;
    g_csr_src[p1] = s4.y;
    g_csr_src[p2] = s4.z;
    g_csr_src[p3] = s4.w;
}

// ---------------- K3: warp per dst node, batched-exp (R16 + chain re-zero) -----
__global__ void __launch_bounds__(256)
k_agg(const float* __restrict__ bias, float* __restrict__ out)
{
    // reset scan-chain + histogram state for the next launch/replay
    if (blockIdx.x == 0 && threadIdx.x < 32) g_chain[threadIdx.x] = 0;

    const int d = (blockIdx.x * 256 + threadIdx.x) >> 5;
    const int lane = threadIdx.x & 31;
    if (d >= N_NODES) return;
    const int q = lane >> 3;
    const int h = lane & 7;
    const int ghead = lane >> 2;

    const uint64_t pol_last  = mk_policy_evict_last();
    const uint64_t pol_first = mk_policy_evict_first();

    const int start = g_off[d], end = g_off[d + 1];
    const float erh = g_er[d * HEADS + h];
    if (lane == 0) g_deg[d] = 0;     // reset histogram for the next graph replay

    float sum = 0.f;
    float4 acc = {0.f, 0.f, 0.f, 0.f};

    for (int base = start; base < end; base += 32) {
        const int idx = base + lane;
        const int myS = (idx < end) ? ldg_i_hint(g_csr_src + idx, pol_first) : 0;
        const int cnt = min(32, end - base);

        for (int t = 0; t < cnt; t += 4) {
            int se = __shfl_sync(0xffffffffu, myS, t + q);
            float a = ldg_f_hint(g_el + se * HEADS + h, pol_last) + erh;
            a = fmaxf(a, 0.f) + NEG_SLOPE * fminf(a, 0.f);
            float ex = (t + q < cnt) ? __expf(a) : 0.f;
            sum += ex;

            #pragma unroll
            for (int u = 0; u < 4; u++) {
                int s = __shfl_sync(0xffffffffu, myS, t + u);
                float exh = __shfl_sync(0xffffffffu, ex, u * 8 + ghead);
                float4 hv = ldg_v4_hint(((const float4*)(g_h + s * HD)) + lane, pol_last);
                acc.x += exh * hv.x; acc.y += exh * hv.y;
                acc.z += exh * hv.z; acc.w += exh * hv.w;
            }
        }
    }

    sum += __shfl_xor_sync(0xffffffffu, sum, 8);
    sum += __shfl_xor_sync(0xffffffffu, sum, 16);
    float sumh = __shfl_sync(0xffffffffu, sum, ghead);

    float inv = (end > start) ? 1.f / sumh : 0.f;
    float4 hd = ldg_v4_hint(((const float4*)(g_h + d * HD)) + lane, pol_last);
    float4 b  = ((const float4*)bias)[lane];
    float4 o;
    o.x = acc.x * inv + hd.x + b.x;
    o.y = acc.y * inv + hd.y + b.y;
    o.z = acc.z * inv + hd.z + b.z;
    o.w = acc.w * inv + hd.w + b.w;
    stg_v4_hint(((float4*)(out + d * HD)) + lane, o, pol_first);
}

// ---------------- launch ---------------------------------------------------------
extern "C" void kernel_launch(void* const* d_in, const int* in_sizes, int n_in,
                              void* d_out, int out_size)
{
    const float* feats  = (const float*)d_in[0];
    const float* W      = (const float*)d_in[1];
    const float* attn_l = (const float*)d_in[2];
    const float* attn_r = (const float*)d_in[3];
    const float* bias   = (const float*)d_in[4];
    const int*   src    = (const int*)d_in[5];
    const int*   dst    = (const int*)d_in[6];
    float* out = (float*)d_out;

    cudaFuncSetAttribute(k_proj, cudaFuncAttributeMaxDynamicSharedMemorySize, PROJ_SMEM);

    int prio_lo = 0, prio_hi = 0;
    cudaDeviceGetStreamPriorityRange(&prio_lo, &prio_hi);

    cudaStream_t side;
    cudaEvent_t ev_fork, ev_join;
    cudaStreamCreateWithPriority(&side, cudaStreamNonBlocking, prio_hi);  // CSR wins SM slots
    cudaEventCreateWithFlags(&ev_fork, cudaEventDisableTiming);
    cudaEventCreateWithFlags(&ev_join, cudaEventDisableTiming);

    cudaEventRecord(ev_fork, 0);
    cudaStreamWaitEvent(side, ev_fork, 0);

    // CSR build chain on high-priority side stream
    k_hist<<<(N_EDGES / 4 + 255) / 256, 256, 0, side>>>(dst);
    k_scan<<<SCAN_BLOCKS, 1024, 0, side>>>();
    k_scatter<<<(N_EDGES / 4 + 255) / 256, 256, 0, side>>>(src, dst);
    cudaEventRecord(ev_join, side);

    // tensor-core projection on the main stream, concurrent with CSR build
    k_proj<<<296, PROJ_BLOCK, PROJ_SMEM>>>(feats, W, attn_l, attn_r);

    cudaStreamWaitEvent(0, ev_join, 0);
    k_agg<<<(N_NODES * 32 + 255) / 256, 256>>>(bias, out);
}